// round 14
// baseline (speedup 1.0000x reference)
#include <cuda_runtime.h>
#include <cstdint>
#include <cstddef>

// ---------------- problem constants ----------------
#define DIM    256
#define BATCH  256
#define KSEQ   2048
#define KC     32                    // K-chunk (e dimension)
#define NCHUNK 8
#define ROWS_CTA 128                 // output columns (n) per CTA: 32 b x 4 k
#define GRID   ((KSEQ * BATCH) / ROWS_CTA)   // 4096
#define NTHREADS 512

// ---------------- smem layout (floats) ----------------
#define LDA      36                  // padded row stride (144 B); LDS.128 at 4-phase floor
#define ASTRIDE  (128 * LDA)         // 4608 floats per A buffer
#define B_OFF    (2 * ASTRIDE)       // 9216: B buffers start
#define BSTRIDE  (256 * LDA)         // 9216 floats per B buffer
#define SMEM_FLOATS (B_OFF + 2 * BSTRIDE)    // 27648 floats
#define SMEM_TOTAL  (SMEM_FLOATS * 4)        // 110592 B
// epilogue overlays:
#define QS_LD    260                 // qc tile stride (32 x 260 floats in A region)
#define RED_OFF  B_OFF               // reduction buffer 128 x 9 floats (in B region)

__device__ float g_qc[BATCH * DIM];  // qc[b][d] = query@Wq^T + bq + bref

// ---------------- helpers ----------------
__device__ __forceinline__ uint32_t smem_u32(const void* p) {
    uint32_t a;
    asm("{ .reg .u64 t; cvta.to.shared.u64 t, %1; cvt.u32.u64 %0, t; }" : "=r"(a) : "l"(p));
    return a;
}
__device__ __forceinline__ uint32_t cvt_tf32(float x) {
    uint32_t r;
    asm("cvt.rna.tf32.f32 %0, %1;" : "=r"(r) : "f"(x));
    return r;
}
__device__ __forceinline__ float tanh_fast(float x) {
    float r;
    asm("tanh.approx.f32 %0, %1;" : "=f"(r) : "f"(x));
    return r;
}
__device__ __forceinline__ void cp_async16(uint32_t saddr, const void* gaddr) {
    asm volatile("cp.async.cg.shared.global [%0], [%1], 16;"
                 :: "r"(saddr), "l"(gaddr) : "memory");
}
__device__ __forceinline__ void mma_tf32(float* d, const uint32_t* a, const uint32_t* b) {
    asm volatile(
        "mma.sync.aligned.m16n8k8.row.col.f32.tf32.tf32.f32 "
        "{%0,%1,%2,%3}, {%4,%5,%6,%7}, {%8,%9}, {%0,%1,%2,%3};"
        : "+f"(d[0]), "+f"(d[1]), "+f"(d[2]), "+f"(d[3])
        : "r"(a[0]), "r"(a[1]), "r"(a[2]), "r"(a[3]), "r"(b[0]), "r"(b[1]));
}

// ---------------- kernel 1: qc precompute ----------------
__global__ void __launch_bounds__(256) qc_kernel(const float* __restrict__ query,
                                                 const float* __restrict__ Wq,
                                                 const float* __restrict__ bq,
                                                 const float* __restrict__ bref) {
    const int b = blockIdx.x;
    const int d = threadIdx.x;
    __shared__ float qrow[DIM];
    qrow[d] = query[b * DIM + d];
    __syncthreads();

    const float4* w4 = reinterpret_cast<const float4*>(Wq + d * DIM);
    float acc = 0.0f;
#pragma unroll 8
    for (int e4 = 0; e4 < DIM / 4; e4++) {
        float4 w = w4[e4];
        const float4 q = *reinterpret_cast<const float4*>(qrow + e4 * 4);
        acc = fmaf(w.x, q.x, acc);
        acc = fmaf(w.y, q.y, acc);
        acc = fmaf(w.z, q.z, acc);
        acc = fmaf(w.w, q.w, acc);
    }
    g_qc[b * DIM + d] = acc + bq[d] + bref[d];
}

// ---------------- kernel 2: mma.sync tf32 GEMM + tanh epilogue ----------------
// D[n,d]: n-tile 128 rows (row r -> b = SB+(r&31), k = SK+(r>>5)), d = 256.
// 16 warps: wn = warp>>3 (n 64-half), wd = warp&7 (d 32-slice). Warp tile 64x32.
// k permutation (shared by A and B, so the GEMM is invariant):
//   physical col quad 16s'+4t+{0,1,2,3}  <->  (step 2s',  mma cols t, t+4),
//                                             (step 2s'+1, mma cols t, t+4)
// -> every fragment read is one aligned LDS.128 at the 4-phase structural floor.
__global__ void __launch_bounds__(NTHREADS, 1) attn_main(const float* __restrict__ enc,
                                                         const float* __restrict__ Wref,
                                                         const float* __restrict__ v,
                                                         float* __restrict__ out) {
    extern __shared__ float sm[];
    const uint32_t sbase = smem_u32(sm);
    const int tid  = threadIdx.x;
    const int lane = tid & 31;
    const int warp = tid >> 5;
    const int g = lane >> 2;          // groupID (row within 8)
    const int t = lane & 3;           // thread-in-group
    const int wn = warp >> 3;         // 0..1
    const int wd = warp & 7;          // 0..7
    const int SB = (blockIdx.x & 7) * 32;
    const int SK = (blockIdx.x >> 3) * 4;

    // ---- cp.async copy mapping (512 threads, 6 x 16B each per chunk) ----
    const int rA  = tid >> 3;
    const int seg = tid & 7;
    const int nA0 = (SK + (rA >> 5)) * 256 + SB + (rA & 31);
    const float* gA0 = enc + (size_t)nA0 * DIM + seg * 4;   // row rA
    const float* gA1 = gA0 + (size_t)512 * DIM;             // row rA+64 (n += 512)
    const float* gB0 = Wref + (size_t)rA * DIM + seg * 4;   // rows rA + 64i
    const uint32_t sAb = sbase + (uint32_t)(rA * LDA + seg * 4) * 4u;
    const uint32_t sBb = sbase + (uint32_t)(B_OFF + rA * LDA + seg * 4) * 4u;

    float acc[4][4][4];
#pragma unroll
    for (int m = 0; m < 4; m++)
#pragma unroll
        for (int j = 0; j < 4; j++)
#pragma unroll
            for (int c4 = 0; c4 < 4; c4++) acc[m][j][c4] = 0.0f;

    // prologue: issue chunk 0
    {
        cp_async16(sAb, gA0);
        cp_async16(sAb + 64u * LDA * 4u, gA1);
#pragma unroll
        for (int i = 0; i < 4; i++)
            cp_async16(sBb + (uint32_t)i * 64u * LDA * 4u, gB0 + (size_t)i * 64 * DIM);
        asm volatile("cp.async.commit_group;" ::: "memory");
    }

    for (int c = 0; c < NCHUNK; c++) {
        if (c + 1 < NCHUNK) {   // issue next chunk into the other buffer
            const int k0 = (c + 1) * KC;
            const uint32_t bo = (uint32_t)((c + 1) & 1);
            const uint32_t sa = sAb + bo * (ASTRIDE * 4u);
            const uint32_t sb2 = sBb + bo * (BSTRIDE * 4u);
            cp_async16(sa, gA0 + k0);
            cp_async16(sa + 64u * LDA * 4u, gA1 + k0);
#pragma unroll
            for (int i = 0; i < 4; i++)
                cp_async16(sb2 + (uint32_t)i * 64u * LDA * 4u, gB0 + (size_t)i * 64 * DIM + k0);
            asm volatile("cp.async.commit_group;" ::: "memory");
            asm volatile("cp.async.wait_group 1;" ::: "memory");
        } else {
            asm volatile("cp.async.wait_group 0;" ::: "memory");
        }
        __syncthreads();

        const float* A = sm + (c & 1) * ASTRIDE + (wn * 64 + g) * LDA;
        const float* B = sm + B_OFF + (c & 1) * BSTRIDE + (wd * 32 + g) * LDA;

#pragma unroll
        for (int sp = 0; sp < 2; sp++) {   // 2 step-pairs (4 k8-steps) per chunk
            const int ko = 16 * sp + 4 * t;
            uint32_t ae[4][4], ao[4][4], be[4][2], bo2[4][2];
#pragma unroll
            for (int m = 0; m < 4; m++) {
                const float4 lo = *reinterpret_cast<const float4*>(A + (16 * m) * LDA + ko);
                const float4 hi = *reinterpret_cast<const float4*>(A + (16 * m + 8) * LDA + ko);
                ae[m][0] = cvt_tf32(lo.x); ae[m][1] = cvt_tf32(hi.x);
                ae[m][2] = cvt_tf32(lo.y); ae[m][3] = cvt_tf32(hi.y);
                ao[m][0] = cvt_tf32(lo.z); ao[m][1] = cvt_tf32(hi.z);
                ao[m][2] = cvt_tf32(lo.w); ao[m][3] = cvt_tf32(hi.w);
            }
#pragma unroll
            for (int j = 0; j < 4; j++) {
                const float4 b = *reinterpret_cast<const float4*>(B + (8 * j) * LDA + ko);
                be[j][0]  = cvt_tf32(b.x); be[j][1]  = cvt_tf32(b.y);
                bo2[j][0] = cvt_tf32(b.z); bo2[j][1] = cvt_tf32(b.w);
            }
#pragma unroll
            for (int m = 0; m < 4; m++)
#pragma unroll
                for (int j = 0; j < 4; j++)
                    mma_tf32(acc[m][j], ae[m], be[j]);
#pragma unroll
            for (int m = 0; m < 4; m++)
#pragma unroll
                for (int j = 0; j < 4; j++)
                    mma_tf32(acc[m][j], ao[m], bo2[j]);
        }
        __syncthreads();   // before next iteration's cp.async overwrites this buffer
    }

    // ---- epilogue ----
    // stage qc tile (32 b x 256 d) into smem (overlays A region)
    {
#pragma unroll
        for (int i = 0; i < 4; i++) {
            const int idx = tid + NTHREADS * i;      // 2048 float4s
            const int r = idx >> 6, c4 = idx & 63;
            *reinterpret_cast<float4*>(sm + r * QS_LD + c4 * 4) =
                *reinterpret_cast<const float4*>(g_qc + (size_t)(SB + r) * DIM + c4 * 4);
        }
    }
    __syncthreads();

    float vv[4][2];
#pragma unroll
    for (int j = 0; j < 4; j++) {
        const int d = wd * 32 + 8 * j + 2 * t;
        vv[j][0] = v[d];
        vv[j][1] = v[d + 1];
    }

    float part[4][2];
#pragma unroll
    for (int m = 0; m < 4; m++) {
#pragma unroll
        for (int h = 0; h < 2; h++) {
            const int row = wn * 64 + 16 * m + 8 * h + g;
            const float* q = sm + (row & 31) * QS_LD + wd * 32 + 2 * t;
            float p = 0.0f;
#pragma unroll
            for (int j = 0; j < 4; j++) {
                p = fmaf(vv[j][0], tanh_fast(acc[m][j][2 * h]     + q[8 * j]),     p);
                p = fmaf(vv[j][1], tanh_fast(acc[m][j][2 * h + 1] + q[8 * j + 1]), p);
            }
            p += __shfl_xor_sync(0xffffffffu, p, 1);
            p += __shfl_xor_sync(0xffffffffu, p, 2);
            part[m][h] = p;
        }
    }

    if (t == 0) {
#pragma unroll
        for (int m = 0; m < 4; m++)
#pragma unroll
            for (int h = 0; h < 2; h++) {
                const int row = wn * 64 + 16 * m + 8 * h + g;
                sm[RED_OFF + row * 9 + wd] = part[m][h];
            }
    }
    __syncthreads();

    if (tid < 128) {
        float u = 0.0f;
#pragma unroll
        for (int r = 0; r < 8; r++) u += sm[RED_OFF + tid * 9 + r];
        out[(size_t)(SB + (tid & 31)) * KSEQ + SK + (tid >> 5)] = 10.0f * tanhf(u);
    }
}

extern "C" void kernel_launch(void* const* d_in, const int* in_sizes, int n_in,
                              void* d_out, int out_size) {
    const float* enc   = (const float*)d_in[0];  // (2048, 256, 256)
    const float* query = (const float*)d_in[1];  // (256, 256)
    const float* Wq    = (const float*)d_in[2];  // (256, 256)
    const float* bq    = (const float*)d_in[3];  // (256,)
    const float* Wref  = (const float*)d_in[4];  // (256, 256)
    const float* bref  = (const float*)d_in[5];  // (256,)
    const float* v     = (const float*)d_in[6];  // (256,)
    float* out = (float*)d_out;                  // (256, 2048)

    cudaFuncSetAttribute(attn_main, cudaFuncAttributeMaxDynamicSharedMemorySize, SMEM_TOTAL);

    qc_kernel<<<BATCH, DIM>>>(query, Wq, bq, bref);
    attn_main<<<GRID, NTHREADS, SMEM_TOTAL>>>(enc, Wref, v, out);
}

// round 16
// speedup vs baseline: 1.0620x; 1.0620x over previous
#include <cuda_runtime.h>
#include <cstdint>
#include <cstddef>

// ---------------- problem constants ----------------
#define DIM    256
#define BATCH  256
#define KSEQ   2048
#define KC     16                    // K-chunk (e dimension)
#define NCHUNK 16
#define ROWS_CTA 128                 // output columns (n) per CTA: 32 b x 4 k
#define GRID   ((KSEQ * BATCH) / ROWS_CTA)   // 4096
#define NTHREADS 512

// ---------------- smem layout (32-bit words) ----------------
// smem holds tf32 bit patterns (converted once at STS time).
// LDA=24: read pair-index (12g+t+4s) mod 16 covers each bank-pair exactly 2x
// -> LDS.64 at the 2-phase structural floor.
#define LDA      24
#define ASTRIDE  (128 * LDA)         // 3072 words per A buffer
#define B_OFF    (2 * ASTRIDE)       // 6144: B buffers start
#define BSTRIDE  (256 * LDA)         // 6144 words per B buffer
#define SMEM_WORDS (B_OFF + 2 * BSTRIDE)     // 18432
#define SMEM_TOTAL (SMEM_WORDS * 4)          // 73728 B
// epilogue overlays (after a full barrier):
#define QS_LD    260                 // qc tile: 32 x 260 floats at word offset 0
#define RED_OFF  8320                // reduction buffer 128 x 9 floats

__device__ float g_qc[BATCH * DIM];  // qc[b][d] = query@Wq^T + bq + bref

// ---------------- helpers ----------------
__device__ __forceinline__ uint32_t smem_u32(const void* p) {
    uint32_t a;
    asm("{ .reg .u64 t; cvta.to.shared.u64 t, %1; cvt.u32.u64 %0, t; }" : "=r"(a) : "l"(p));
    return a;
}
__device__ __forceinline__ uint32_t cvt_tf32(float x) {
    uint32_t r;
    asm("cvt.rna.tf32.f32 %0, %1;" : "=r"(r) : "f"(x));
    return r;
}
__device__ __forceinline__ float tanh_fast(float x) {
    float r;
    asm("tanh.approx.f32 %0, %1;" : "=f"(r) : "f"(x));
    return r;
}
__device__ __forceinline__ void sts_tf32x4(uint32_t addr, float4 v) {
    uint32_t a = cvt_tf32(v.x), b = cvt_tf32(v.y), c = cvt_tf32(v.z), d = cvt_tf32(v.w);
    asm volatile("st.shared.v4.b32 [%0], {%1,%2,%3,%4};"
                 :: "r"(addr), "r"(a), "r"(b), "r"(c), "r"(d) : "memory");
}
__device__ __forceinline__ void mma_tf32(float* d, const uint32_t* a, const uint32_t* b) {
    asm volatile(
        "mma.sync.aligned.m16n8k8.row.col.f32.tf32.tf32.f32 "
        "{%0,%1,%2,%3}, {%4,%5,%6,%7}, {%8,%9}, {%0,%1,%2,%3};"
        : "+f"(d[0]), "+f"(d[1]), "+f"(d[2]), "+f"(d[3])
        : "r"(a[0]), "r"(a[1]), "r"(a[2]), "r"(a[3]), "r"(b[0]), "r"(b[1]));
}

// ---------------- kernel 1: qc precompute ----------------
__global__ void __launch_bounds__(256) qc_kernel(const float* __restrict__ query,
                                                 const float* __restrict__ Wq,
                                                 const float* __restrict__ bq,
                                                 const float* __restrict__ bref) {
    const int b = blockIdx.x;
    const int d = threadIdx.x;
    __shared__ float qrow[DIM];
    qrow[d] = query[b * DIM + d];
    __syncthreads();

    const float4* w4 = reinterpret_cast<const float4*>(Wq + d * DIM);
    float acc = 0.0f;
#pragma unroll 8
    for (int e4 = 0; e4 < DIM / 4; e4++) {
        float4 w = w4[e4];
        const float4 q = *reinterpret_cast<const float4*>(qrow + e4 * 4);
        acc = fmaf(w.x, q.x, acc);
        acc = fmaf(w.y, q.y, acc);
        acc = fmaf(w.z, q.z, acc);
        acc = fmaf(w.w, q.w, acc);
    }
    g_qc[b * DIM + d] = acc + bq[d] + bref[d];
}

// ---------------- kernel 2: mma.sync tf32 GEMM + tanh epilogue ----------------
// D[n,d]: n-tile 128 rows (row r -> b = SB+(r&31), k = SK+(r>>5)), d = 256.
// 16 warps: wn = warp>>3 (n 64-half), wd = warp&7 (d 32-slice). Warp tile 64x32.
// k-pair permutation (shared by A and B -> GEMM invariant):
//   mma k-cols (t, t+4) <-> physical cols (2t, 2t+1).
// smem holds tf32 (converted at STS) -> inner loop is pure LDS.64 + MMA.
__global__ void __launch_bounds__(NTHREADS, 1) attn_main(const float* __restrict__ enc,
                                                         const float* __restrict__ Wref,
                                                         const float* __restrict__ v,
                                                         float* __restrict__ out) {
    extern __shared__ float sm[];
    uint32_t* const smu = reinterpret_cast<uint32_t*>(sm);
    const uint32_t sbase = smem_u32(sm);
    const int tid  = threadIdx.x;
    const int lane = tid & 31;
    const int warp = tid >> 5;
    const int g = lane >> 2;          // groupID (row within 8)
    const int t = lane & 3;           // thread-in-group
    const int wn = warp >> 3;         // 0..1
    const int wd = warp & 7;          // 0..7
    const int SB = (blockIdx.x & 7) * 32;
    const int SK = (blockIdx.x >> 3) * 4;

    // ---- staging mapping: thread -> (row rS = tid>>2, quad qS = tid&3) ----
    // A: 128 rows x 4 quads (1 float4/thread/chunk); B: 256 rows -> rows rS and rS+128.
    const int rS = tid >> 2;
    const int qS = tid & 3;
    const int nA = (SK + (rS >> 5)) * 256 + SB + (rS & 31);
    const float* gA  = enc + (size_t)nA * DIM + qS * 4;
    const float* gB0 = Wref + (size_t)rS * DIM + qS * 4;
    const float* gB1 = gB0 + (size_t)128 * DIM;
    const uint32_t stsA  = sbase + (uint32_t)(rS * LDA + qS * 4) * 4u;
    const uint32_t stsB0 = sbase + (uint32_t)(B_OFF + rS * LDA + qS * 4) * 4u;
    const uint32_t stsB1 = stsB0 + 128u * LDA * 4u;

    float acc[4][4][4];
#pragma unroll
    for (int m = 0; m < 4; m++)
#pragma unroll
        for (int j = 0; j < 4; j++)
#pragma unroll
            for (int c4 = 0; c4 < 4; c4++) acc[m][j][c4] = 0.0f;

    // ---- prologue: chunk 0 -> buf0; prefetch A chunks 1,2 ----
    float4 ra_sts, ra_pre, rb0, rb1;
    ra_sts = *reinterpret_cast<const float4*>(gA);
    rb0    = *reinterpret_cast<const float4*>(gB0);
    rb1    = *reinterpret_cast<const float4*>(gB1);
    sts_tf32x4(stsA,  ra_sts);
    sts_tf32x4(stsB0, rb0);
    sts_tf32x4(stsB1, rb1);
    ra_sts = *reinterpret_cast<const float4*>(gA + KC);        // A chunk 1
    ra_pre = *reinterpret_cast<const float4*>(gA + 2 * KC);    // A chunk 2
    __syncthreads();

    for (int c = 0; c < NCHUNK; c++) {
        if (c + 1 < NCHUNK) {   // B one chunk ahead (L2-resident, ~250 cyc)
            rb0 = *reinterpret_cast<const float4*>(gB0 + (c + 1) * KC);
            rb1 = *reinterpret_cast<const float4*>(gB1 + (c + 1) * KC);
        }

        const uint32_t* A = smu + (c & 1) * ASTRIDE + (wn * 64 + g) * LDA;
        const uint32_t* B = smu + B_OFF + (c & 1) * BSTRIDE + (wd * 32 + g) * LDA;

#pragma unroll
        for (int s = 0; s < 2; s++) {      // 2 k8-steps per 16-chunk
            const int ko = 8 * s + 2 * t;  // physical col pair base
            uint32_t af[4][4], bf[4][2];
#pragma unroll
            for (int m = 0; m < 4; m++) {
                const uint2 lo = *reinterpret_cast<const uint2*>(A + (16 * m) * LDA + ko);
                const uint2 hi = *reinterpret_cast<const uint2*>(A + (16 * m + 8) * LDA + ko);
                af[m][0] = lo.x; af[m][1] = hi.x; af[m][2] = lo.y; af[m][3] = hi.y;
            }
#pragma unroll
            for (int j = 0; j < 4; j++) {
                const uint2 b = *reinterpret_cast<const uint2*>(B + (8 * j) * LDA + ko);
                bf[j][0] = b.x; bf[j][1] = b.y;
            }
#pragma unroll
            for (int m = 0; m < 4; m++)
#pragma unroll
                for (int j = 0; j < 4; j++)
                    mma_tf32(acc[m][j], af[m], bf[j]);
        }

        if (c + 1 < NCHUNK) {
            __syncthreads();   // all warps done reading buf (c+1)&1 (chunk c-1)
            const uint32_t aoff = (uint32_t)((c + 1) & 1) * (ASTRIDE * 4u);
            const uint32_t boff = (uint32_t)((c + 1) & 1) * (BSTRIDE * 4u);
            sts_tf32x4(stsA  + aoff, ra_sts);
            sts_tf32x4(stsB0 + boff, rb0);
            sts_tf32x4(stsB1 + boff, rb1);
            ra_sts = ra_pre;
            if (c + 3 < NCHUNK)   // A two chunks ahead (DRAM ~600 cyc span)
                ra_pre = *reinterpret_cast<const float4*>(gA + (c + 3) * KC);
            __syncthreads();   // stores visible before chunk c+1 reads
        }
    }
    __syncthreads();   // mainloop smem reads done before epilogue overlay

    // ---- epilogue ----
    // stage qc tile (32 b x 256 d) into smem word offset 0
    {
#pragma unroll
        for (int i = 0; i < 4; i++) {
            const int idx = tid + NTHREADS * i;      // 2048 float4s
            const int r = idx >> 6, c4 = idx & 63;
            *reinterpret_cast<float4*>(sm + r * QS_LD + c4 * 4) =
                *reinterpret_cast<const float4*>(g_qc + (size_t)(SB + r) * DIM + c4 * 4);
        }
    }
    __syncthreads();

    float vv[4][2];
#pragma unroll
    for (int j = 0; j < 4; j++) {
        const int d = wd * 32 + 8 * j + 2 * t;
        vv[j][0] = v[d];
        vv[j][1] = v[d + 1];
    }

    float part[4][2];
#pragma unroll
    for (int m = 0; m < 4; m++) {
#pragma unroll
        for (int h = 0; h < 2; h++) {
            const int row = wn * 64 + 16 * m + 8 * h + g;
            const float* q = sm + (row & 31) * QS_LD + wd * 32 + 2 * t;
            float p = 0.0f;
#pragma unroll
            for (int j = 0; j < 4; j++) {
                p = fmaf(vv[j][0], tanh_fast(acc[m][j][2 * h]     + q[8 * j]),     p);
                p = fmaf(vv[j][1], tanh_fast(acc[m][j][2 * h + 1] + q[8 * j + 1]), p);
            }
            p += __shfl_xor_sync(0xffffffffu, p, 1);
            p += __shfl_xor_sync(0xffffffffu, p, 2);
            part[m][h] = p;
        }
    }

    if (t == 0) {
#pragma unroll
        for (int m = 0; m < 4; m++)
#pragma unroll
            for (int h = 0; h < 2; h++) {
                const int row = wn * 64 + 16 * m + 8 * h + g;
                sm[RED_OFF + row * 9 + wd] = part[m][h];
            }
    }
    __syncthreads();

    if (tid < 128) {
        float u = 0.0f;
#pragma unroll
        for (int r = 0; r < 8; r++) u += sm[RED_OFF + tid * 9 + r];
        out[(size_t)(SB + (tid & 31)) * KSEQ + SK + (tid >> 5)] = 10.0f * tanhf(u);
    }
}

extern "C" void kernel_launch(void* const* d_in, const int* in_sizes, int n_in,
                              void* d_out, int out_size) {
    const float* enc   = (const float*)d_in[0];  // (2048, 256, 256)
    const float* query = (const float*)d_in[1];  // (256, 256)
    const float* Wq    = (const float*)d_in[2];  // (256, 256)
    const float* bq    = (const float*)d_in[3];  // (256,)
    const float* Wref  = (const float*)d_in[4];  // (256, 256)
    const float* bref  = (const float*)d_in[5];  // (256,)
    const float* v     = (const float*)d_in[6];  // (256,)
    float* out = (float*)d_out;                  // (256, 2048)

    cudaFuncSetAttribute(attn_main, cudaFuncAttributeMaxDynamicSharedMemorySize, SMEM_TOTAL);

    qc_kernel<<<BATCH, DIM>>>(query, Wq, bq, bref);
    attn_main<<<GRID, NTHREADS, SMEM_TOTAL>>>(enc, Wref, v, out);
}